// round 2
// baseline (speedup 1.0000x reference)
#include <cuda_runtime.h>
#include <cuda_bf16.h>
#include <cstdint>

// Problem constants
#define BATCH 256
#define CW    8192
#define NC    64          // dim_codes
#define NS    4096        // dict_size
#define NE    128         // dim_embed

#define BM 128            // rows per block (b-tile)
#define SN 128            // dict entries per chunk
#define NCHUNK (NS / SN)  // 32
#define NTHREADS 512

// out layout: [BATCH*CW] embed  ++  [BATCH*NC*NS] one-hot
#define EMBED_ELEMS (BATCH * CW)            // 2,097,152

__device__ int g_argmin[BATCH * NC];

// ---- packed f32x2 helpers (PTX-only on sm_103a; ptxas never auto-fuses) ----
__device__ __forceinline__ unsigned long long pack2(float v) {
    unsigned long long r;
    unsigned int u = __float_as_uint(v);
    asm("mov.b64 %0, {%1, %1};" : "=l"(r) : "r"(u));
    return r;
}
__device__ __forceinline__ void ffma2(unsigned long long& d, unsigned long long a,
                                      unsigned long long b) {
    asm("fma.rn.f32x2 %0, %1, %2, %0;" : "+l"(d) : "l"(a), "l"(b));
}
__device__ __forceinline__ void unpack2(unsigned long long p, float& lo, float& hi) {
    unsigned int a, b;
    asm("mov.b64 {%0, %1}, %2;" : "=r"(a), "=r"(b) : "l"(p));
    lo = __uint_as_float(a);
    hi = __uint_as_float(b);
}

// Kernel 1: fused distance GEMM + argmin.
// score(b,c,s) = |d_cs|^2 - 2 * x_bc . d_cs   (|x|^2 dropped: argmin-invariant)
__global__ __launch_bounds__(NTHREADS, 1)
void vq_argmin_kernel(const float* __restrict__ x, const float* __restrict__ dict) {
    extern __shared__ float sm[];
    float* Xs  = sm;               // [128][128] k-major: Xs[k*128 + r]
    float* Ds  = sm + 16384;       // [128][128] k-major, group-swizzled
    float* dsq = sm + 32768;       // [128] |d|^2 for current chunk

    const int tid = threadIdx.x;
    const int c   = blockIdx.x;                 // codebook index
    const int b0  = blockIdx.y * BM;            // batch tile start

    const int tx   = tid & 15;                  // 0..15 -> column group
    const int ty   = tid >> 4;                  // 0..31 -> row group
    const int r0   = ty * 4;                    // 4 rows per thread
    const int col0 = tx * 8;                    // 8 logical dict cols per thread

    // ---- load X tile transposed: Xs[k][r] ----
    {
        const int r = tid >> 2;                 // 0..127
        const int q = tid & 3;                  // 0..3 (k quarter)
        const float* src = x + (size_t)(b0 + r) * CW + c * NE + q * 32;
        #pragma unroll
        for (int j = 0; j < 8; ++j) {
            float4 v = *(const float4*)(src + j * 4);
            int k = q * 32 + j * 4;
            Xs[(k + 0) * 128 + r] = v.x;
            Xs[(k + 1) * 128 + r] = v.y;
            Xs[(k + 2) * 128 + r] = v.z;
            Xs[(k + 3) * 128 + r] = v.w;
        }
    }

    unsigned long long acc[4][4];
    #pragma unroll
    for (int i = 0; i < 4; ++i)
        #pragma unroll
        for (int j = 0; j < 4; ++j) acc[i][j] = 0ULL;

    float minv[4];
    int   mini[4];
    #pragma unroll
    for (int i = 0; i < 4; ++i) { minv[i] = 3.402823466e38f; mini[i] = 0; }

    // dict loading assignment: thread -> (si row within chunk, k quarter)
    const int si = tid >> 2;                    // 0..127
    const int q  = tid & 3;                     // 0..3
    const int g  = si >> 3;                     // group of 8 cols
    const int s3 = si & 7;
    const float* dbase = dict + (size_t)c * NS * NE + q * 32;

    float4 ld[8];
    // prefetch chunk 0
    {
        const float* src = dbase + (size_t)si * NE;
        #pragma unroll
        for (int j = 0; j < 8; ++j) ld[j] = *(const float4*)(src + j * 4);
    }

    for (int ch = 0; ch < NCHUNK; ++ch) {
        // ---- |d|^2 partial (from registers) + swizzled transposed STS ----
        float p = 0.f;
        #pragma unroll
        for (int j = 0; j < 8; ++j) {
            p = fmaf(ld[j].x, ld[j].x, p);
            p = fmaf(ld[j].y, ld[j].y, p);
            p = fmaf(ld[j].z, ld[j].z, p);
            p = fmaf(ld[j].w, ld[j].w, p);
        }
        p += __shfl_xor_sync(0xffffffffu, p, 1);
        p += __shfl_xor_sync(0xffffffffu, p, 2);
        if (q == 0) dsq[si] = p;

        // physical column: XOR-swizzle group by k-quarter -> STS conflict-free
        const int pc = (((g ^ q) & 15) << 3) | s3;
        #pragma unroll
        for (int j = 0; j < 8; ++j) {
            int k = q * 32 + j * 4;
            Ds[(k + 0) * 128 + pc] = ld[j].x;
            Ds[(k + 1) * 128 + pc] = ld[j].y;
            Ds[(k + 2) * 128 + pc] = ld[j].z;
            Ds[(k + 3) * 128 + pc] = ld[j].w;
        }
        __syncthreads();

        // prefetch next chunk (LDGs overlap the compute below)
        if (ch + 1 < NCHUNK) {
            const float* src = dbase + (size_t)((ch + 1) * SN + si) * NE;
            #pragma unroll
            for (int j = 0; j < 8; ++j) ld[j] = *(const float4*)(src + j * 4);
        }

        // ---- cross-term GEMM: acc += x * d  (packed f32x2) ----
        #pragma unroll 8
        for (int kk = 0; kk < NE; ++kk) {
            const float4 xv = *(const float4*)&Xs[kk * 128 + r0];
            unsigned long long a0 = pack2(xv.x);
            unsigned long long a1 = pack2(xv.y);
            unsigned long long a2 = pack2(xv.z);
            unsigned long long a3 = pack2(xv.w);
            const int pg = ((tx ^ (kk >> 5)) & 15) << 3;  // de-swizzle read
            const ulonglong2 dA = *(const ulonglong2*)&Ds[kk * 128 + pg];
            const ulonglong2 dB = *(const ulonglong2*)&Ds[kk * 128 + pg + 4];
            ffma2(acc[0][0], a0, dA.x); ffma2(acc[0][1], a0, dA.y);
            ffma2(acc[0][2], a0, dB.x); ffma2(acc[0][3], a0, dB.y);
            ffma2(acc[1][0], a1, dA.x); ffma2(acc[1][1], a1, dA.y);
            ffma2(acc[1][2], a1, dB.x); ffma2(acc[1][3], a1, dB.y);
            ffma2(acc[2][0], a2, dA.x); ffma2(acc[2][1], a2, dA.y);
            ffma2(acc[2][2], a2, dB.x); ffma2(acc[2][3], a2, dB.y);
            ffma2(acc[3][0], a3, dA.x); ffma2(acc[3][1], a3, dA.y);
            ffma2(acc[3][2], a3, dB.x); ffma2(acc[3][3], a3, dB.y);
        }

        // ---- score & running argmin (ascending index order -> first-min kept) ----
        const int sbase = ch * SN + col0;
        #pragma unroll
        for (int i = 0; i < 4; ++i) {
            #pragma unroll
            for (int jp = 0; jp < 4; ++jp) {
                float lo, hi;
                unpack2(acc[i][jp], lo, hi);
                const float d0 = dsq[col0 + jp * 2];
                const float d1 = dsq[col0 + jp * 2 + 1];
                const float sc0 = fmaf(-2.f, lo, d0);
                const float sc1 = fmaf(-2.f, hi, d1);
                const int s_0 = sbase + jp * 2;
                if (sc0 < minv[i]) { minv[i] = sc0; mini[i] = s_0; }
                if (sc1 < minv[i]) { minv[i] = sc1; mini[i] = s_0 + 1; }
                acc[i][jp] = 0ULL;
            }
        }
        __syncthreads();   // readers done before next chunk's STS
    }

    // ---- reduce argmin across the 16 tx lanes sharing each row ----
    #pragma unroll
    for (int i = 0; i < 4; ++i) {
        float v  = minv[i];
        int   ix = mini[i];
        #pragma unroll
        for (int off = 8; off; off >>= 1) {
            float ov = __shfl_xor_sync(0xffffffffu, v, off);
            int   oi = __shfl_xor_sync(0xffffffffu, ix, off);
            if (ov < v || (ov == v && oi < ix)) { v = ov; ix = oi; }
        }
        if (tx == 0) g_argmin[(b0 + r0 + i) * NC + c] = ix;
    }
}

// Kernel 2: gather codewords + stream the one-hot rows (zeros + single 1.0).
__global__ __launch_bounds__(256)
void vq_output_kernel(const float* __restrict__ dict, float* __restrict__ out) {
    const int bc = blockIdx.x;        // b*NC + c
    const int b  = bc >> 6;
    const int c  = bc & 63;
    const int idx = g_argmin[bc];
    const int t  = threadIdx.x;

    if (t < 32) {   // 32 * float4 = 128 floats: gathered codeword
        const float4* src = (const float4*)(dict + ((size_t)c * NS + idx) * NE);
        float4* dst = (float4*)(out + (size_t)b * CW + c * NE);
        dst[t] = src[t];
    }

    float4* oh = (float4*)(out + (size_t)EMBED_ELEMS + (size_t)bc * NS);
    const int qi = idx >> 2;
    const int ri = idx & 3;
    #pragma unroll
    for (int it = 0; it < 4; ++it) {
        const int pidx = t + it * 256;         // 0..1023 float4 slots
        float4 v = make_float4(0.f, 0.f, 0.f, 0.f);
        if (pidx == qi) {
            v.x = (ri == 0) ? 1.f : 0.f;
            v.y = (ri == 1) ? 1.f : 0.f;
            v.z = (ri == 2) ? 1.f : 0.f;
            v.w = (ri == 3) ? 1.f : 0.f;
        }
        oh[pidx] = v;
    }
}

extern "C" void kernel_launch(void* const* d_in, const int* in_sizes, int n_in,
                              void* d_out, int out_size) {
    const float* x    = (const float*)d_in[0];   // [256, 8192]
    const float* dict = (const float*)d_in[1];   // [64, 4096, 128]
    float* out = (float*)d_out;

    const int smem_bytes = (16384 + 16384 + 128) * sizeof(float);  // 131,584 B
    cudaFuncSetAttribute(vq_argmin_kernel,
                         cudaFuncAttributeMaxDynamicSharedMemorySize, smem_bytes);

    vq_argmin_kernel<<<dim3(NC, BATCH / BM), NTHREADS, smem_bytes>>>(x, dict);
    vq_output_kernel<<<BATCH * NC, 256>>>(dict, out);
}

// round 4
// speedup vs baseline: 1.5443x; 1.5443x over previous
#include <cuda_runtime.h>
#include <cuda_bf16.h>
#include <cstdint>

// Problem constants
#define BATCH 256
#define CW    8192
#define NC    64
#define NS    4096
#define NE    128
#define BM    128            // batch rows per CTA
#define BN    64             // dict entries per chunk
#define NCH   (NS / BN)      // 64 chunks
#define NTH   256

#define EMBED_ELEMS (BATCH * CW)

__device__ int g_argmin[BATCH * NC];

// ---- smem layout (bytes) ----
// XF: [16 ksteps][128 rows][4 tg] uint4  = 131072
// BF: [16 ksteps][64 rows][4 tg] uint4   = 65536
// dsq: 64 floats                          = 256
// wmin: [2][128] float, widx: [2][128] int = 2048
#define SM_XF   0
#define SM_BF   131072
#define SM_DSQ  196608
#define SM_WMIN 196864
#define SM_WIDX 197888
#define SM_TOTAL 198912

static __device__ __forceinline__ uint32_t cvt_tf32(float f) {
    uint32_t u;
    asm("cvt.rna.tf32.f32 %0, %1;" : "=r"(u) : "f"(f));
    return u;
}

static __device__ __forceinline__ void mma_tf32(float4& c, uint32_t a0, uint32_t a1,
                                                uint32_t a2, uint32_t a3,
                                                uint32_t b0, uint32_t b1) {
    asm("mma.sync.aligned.m16n8k8.row.col.f32.tf32.tf32.f32 "
        "{%0,%1,%2,%3}, {%4,%5,%6,%7}, {%8,%9}, {%0,%1,%2,%3};"
        : "+f"(c.x), "+f"(c.y), "+f"(c.z), "+f"(c.w)
        : "r"(a0), "r"(a1), "r"(a2), "r"(a3), "r"(b0), "r"(b1));
}

// split f -> (hi, lo) tf32 bit patterns
static __device__ __forceinline__ void split_tf32(float f, uint32_t& h, uint32_t& l) {
    h = cvt_tf32(f);
    l = cvt_tf32(f - __uint_as_float(h));
}

// ============ Kernel 1: 3xTF32 mma.sync distance GEMM + fused argmin ============
__global__ __launch_bounds__(NTH, 1)
void vq_argmin_mma(const float* __restrict__ x, const float* __restrict__ dict) {
    extern __shared__ char smem[];
    uint4* XF = (uint4*)(smem + SM_XF);
    uint4* BF = (uint4*)(smem + SM_BF);
    float* dsq = (float*)(smem + SM_DSQ);
    float* wmin = (float*)(smem + SM_WMIN);
    int*   widx = (int*)(smem + SM_WIDX);

    const int tid  = threadIdx.x;
    const int wid  = tid >> 5;
    const int lane = tid & 31;
    const int gid  = lane >> 2;     // 0..7
    const int tg   = lane & 3;      // 0..3
    const int m0   = (wid & 3) * 32;   // warp M origin
    const int wn   = wid >> 2;         // 0..1
    const int n0   = wn * 32;          // warp N origin

    const int c  = blockIdx.x;
    const int b0 = blockIdx.y * BM;

    // ---- XF fill: convert x tile once into A-fragment layout ----
    {
        const int r = tid >> 1;        // 0..127
        const int half = tid & 1;      // 0..1 (k half: 64 cols)
        const float* xr = x + (size_t)(b0 + r) * CW + (size_t)c * NE + half * 64;
        float4 xv[16];
        #pragma unroll
        for (int j = 0; j < 16; ++j) xv[j] = *(const float4*)(xr + j * 4);
        const float* pf = (const float*)xv;
        #pragma unroll
        for (int ksl = 0; ksl < 8; ++ksl) {
            const int ks = half * 8 + ksl;
            #pragma unroll
            for (int cc = 0; cc < 4; ++cc) {
                const int kk = ksl * 8 + cc;
                uint32_t h0, l0, h1, l1;
                split_tf32(pf[kk],     h0, l0);
                split_tf32(pf[kk + 4], h1, l1);
                XF[ks * 512 + r * 4 + cc] = make_uint4(h0, h1, l0, l1);
            }
        }
    }

    // ---- per-thread state ----
    float4 acc[2][4];
    #pragma unroll
    for (int mt = 0; mt < 2; ++mt)
        #pragma unroll
        for (int nt = 0; nt < 4; ++nt) acc[mt][nt] = make_float4(0.f, 0.f, 0.f, 0.f);

    float minv[4];
    int   mini[4];
    #pragma unroll
    for (int i = 0; i < 4; ++i) { minv[i] = 3.402823466e38f; mini[i] = 0; }

    // dict conversion role: 4 threads per dict row
    const int dn   = tid >> 2;     // 0..63 (row within chunk)
    const int tseg = tid & 3;      // 0..3  (32-col segment)
    const float* dbase = dict + (size_t)c * NS * NE + tseg * 32;

    float4 pre[8];
    {   // prefetch chunk 0
        const float* src = dbase + (size_t)dn * NE;
        #pragma unroll
        for (int j = 0; j < 8; ++j) pre[j] = *(const float4*)(src + j * 4);
    }

    for (int s = 0; s < NCH; ++s) {
        // ---- convert dict chunk -> BF fragment layout + |d|^2 ----
        {
            const float* pf = (const float*)pre;
            float ss = 0.f;
            #pragma unroll
            for (int i = 0; i < 32; ++i) ss = fmaf(pf[i], pf[i], ss);
            #pragma unroll
            for (int jk = 0; jk < 4; ++jk) {
                #pragma unroll
                for (int cc = 0; cc < 4; ++cc) {
                    const int kk = jk * 8 + cc;
                    uint32_t h0, l0, h1, l1;
                    split_tf32(pf[kk],     h0, l0);
                    split_tf32(pf[kk + 4], h1, l1);
                    BF[(tseg * 4 + jk) * 256 + dn * 4 + cc] = make_uint4(h0, h1, l0, l1);
                }
            }
            ss += __shfl_xor_sync(0xffffffffu, ss, 1);
            ss += __shfl_xor_sync(0xffffffffu, ss, 2);
            if (tseg == 0) dsq[dn] = ss;
        }
        __syncthreads();

        // ---- prefetch next chunk (overlaps mma phase) ----
        if (s + 1 < NCH) {
            const float* src = dbase + (size_t)((s + 1) * BN + dn) * NE;
            #pragma unroll
            for (int j = 0; j < 8; ++j) pre[j] = *(const float4*)(src + j * 4);
        }

        // ---- mma phase: 16 k-steps x (2m x 4n) x 3 passes ----
        #pragma unroll 4
        for (int ks = 0; ks < 16; ++ks) {
            uint4 A0[2], A1[2], Bv[4];
            #pragma unroll
            for (int mt = 0; mt < 2; ++mt) {
                A0[mt] = XF[ks * 512 + (m0 + mt * 16 + gid) * 4 + tg];
                A1[mt] = XF[ks * 512 + (m0 + mt * 16 + 8 + gid) * 4 + tg];
            }
            #pragma unroll
            for (int nt = 0; nt < 4; ++nt)
                Bv[nt] = BF[ks * 256 + (n0 + nt * 8 + gid) * 4 + tg];

            #pragma unroll
            for (int mt = 0; mt < 2; ++mt) {
                #pragma unroll
                for (int nt = 0; nt < 4; ++nt) {
                    // hi*hi
                    mma_tf32(acc[mt][nt], A0[mt].x, A1[mt].x, A0[mt].y, A1[mt].y,
                             Bv[nt].x, Bv[nt].y);
                    // lo*hi
                    mma_tf32(acc[mt][nt], A0[mt].z, A1[mt].z, A0[mt].w, A1[mt].w,
                             Bv[nt].x, Bv[nt].y);
                    // hi*lo
                    mma_tf32(acc[mt][nt], A0[mt].x, A1[mt].x, A0[mt].y, A1[mt].y,
                             Bv[nt].z, Bv[nt].w);
                }
            }
        }

        // ---- epilogue: score + running argmin, reset acc ----
        const int sbase = s * BN;
        #pragma unroll
        for (int mt = 0; mt < 2; ++mt) {
            #pragma unroll
            for (int nt = 0; nt < 4; ++nt) {
                const int colb = n0 + nt * 8 + 2 * tg;
                const float d0 = dsq[colb];
                const float d1 = dsq[colb + 1];
                float4 a = acc[mt][nt];
                const int i0 = sbase + colb;
                // row gid  (slot mt*2)
                {
                    float s0 = fmaf(-2.f, a.x, d0);
                    float s1 = fmaf(-2.f, a.y, d1);
                    if (s0 < minv[mt * 2]) { minv[mt * 2] = s0; mini[mt * 2] = i0; }
                    if (s1 < minv[mt * 2]) { minv[mt * 2] = s1; mini[mt * 2] = i0 + 1; }
                }
                // row gid+8 (slot mt*2+1)
                {
                    float s0 = fmaf(-2.f, a.z, d0);
                    float s1 = fmaf(-2.f, a.w, d1);
                    if (s0 < minv[mt * 2 + 1]) { minv[mt * 2 + 1] = s0; mini[mt * 2 + 1] = i0; }
                    if (s1 < minv[mt * 2 + 1]) { minv[mt * 2 + 1] = s1; mini[mt * 2 + 1] = i0 + 1; }
                }
                acc[mt][nt] = make_float4(0.f, 0.f, 0.f, 0.f);
            }
        }
        __syncthreads();   // BF/dsq reuse safety
    }

    // ---- reduce across tg lanes (same row), then across the 2 n-warps ----
    #pragma unroll
    for (int slot = 0; slot < 4; ++slot) {
        float v  = minv[slot];
        int   ix = mini[slot];
        #pragma unroll
        for (int off = 1; off <= 2; off <<= 1) {
            float ov = __shfl_xor_sync(0xffffffffu, v, off);
            int   oi = __shfl_xor_sync(0xffffffffu, ix, off);
            if (ov < v || (ov == v && oi < ix)) { v = ov; ix = oi; }
        }
        if (tg == 0) {
            const int r = m0 + (slot >> 1) * 16 + (slot & 1) * 8 + gid;
            wmin[wn * 128 + r] = v;
            widx[wn * 128 + r] = ix;
        }
    }
    __syncthreads();
    if (tid < 128) {
        const float v0 = wmin[tid], v1 = wmin[128 + tid];
        const int   i0 = widx[tid], i1 = widx[128 + tid];
        int best = (v1 < v0 || (v1 == v0 && i1 < i0)) ? i1 : i0;
        g_argmin[(size_t)(b0 + tid) * NC + c] = best;
    }
}

// ============ Kernel 2: gather codewords + stream one-hot ============
__global__ __launch_bounds__(256)
void vq_output_kernel(const float* __restrict__ dict, float* __restrict__ out) {
    const int bc = blockIdx.x;        // b*NC + c
    const int b  = bc >> 6;
    const int c  = bc & 63;
    const int idx = g_argmin[bc];
    const int t  = threadIdx.x;

    if (t < 32) {
        const float4* src = (const float4*)(dict + ((size_t)c * NS + idx) * NE);
        float4* dst = (float4*)(out + (size_t)b * CW + c * NE);
        dst[t] = src[t];
    }

    float4* oh = (float4*)(out + (size_t)EMBED_ELEMS + (size_t)bc * NS);
    const int qi = idx >> 2;
    const int ri = idx & 3;
    #pragma unroll
    for (int it = 0; it < 4; ++it) {
        const int pidx = t + it * 256;
        float4 v = make_float4(0.f, 0.f, 0.f, 0.f);
        if (pidx == qi) {
            v.x = (ri == 0) ? 1.f : 0.f;
            v.y = (ri == 1) ? 1.f : 0.f;
            v.z = (ri == 2) ? 1.f : 0.f;
            v.w = (ri == 3) ? 1.f : 0.f;
        }
        oh[pidx] = v;
    }
}

extern "C" void kernel_launch(void* const* d_in, const int* in_sizes, int n_in,
                              void* d_out, int out_size) {
    const float* x    = (const float*)d_in[0];   // [256, 8192]
    const float* dict = (const float*)d_in[1];   // [64, 4096, 128]
    float* out = (float*)d_out;

    cudaFuncSetAttribute(vq_argmin_mma,
                         cudaFuncAttributeMaxDynamicSharedMemorySize, SM_TOTAL);

    vq_argmin_mma<<<dim3(NC, BATCH / BM), NTH, SM_TOTAL>>>(x, dict);
    vq_output_kernel<<<BATCH * NC, 256>>>(dict, out);
}

// round 5
// speedup vs baseline: 2.7252x; 1.7647x over previous
#include <cuda_runtime.h>
#include <cuda_fp16.h>
#include <cstdint>

// Problem constants
#define BATCH 256
#define CW    8192
#define NC    64
#define NS    4096
#define NE    128
#define BM    128            // batch rows per CTA
#define BN    64             // dict entries per chunk
#define NCH   (NS / BN)      // 64 chunks
#define KS    8              // k-steps of 16
#define NTH   256

#define EMBED_ELEMS (BATCH * CW)
#define INV4096 2.44140625e-4f

__device__ int g_argmin[BATCH * NC];

// ---- smem layout (bytes) ----
// XF: [8 ks][128 r][4 tg] uint4 = 65536   (fp16 hi+lo A fragments)
// BF: 2 x [8 ks][64 n][4 tg] uint4 = 65536 (double-buffered B fragments)
// dsq: [2][64] float = 512
// wmin/widx: [2][128] = 1024 each
#define SM_XF   0
#define SM_BF   65536
#define SM_DSQ  131072
#define SM_WMIN 131584
#define SM_WIDX 132608
#define SM_TOTAL 133632

static __device__ __forceinline__ void mma_f16(float4& c, uint32_t a0, uint32_t a1,
                                               uint32_t a2, uint32_t a3,
                                               uint32_t b0, uint32_t b1) {
    asm("mma.sync.aligned.m16n8k16.row.col.f32.f16.f16.f32 "
        "{%0,%1,%2,%3}, {%4,%5,%6,%7}, {%8,%9}, {%0,%1,%2,%3};"
        : "+f"(c.x), "+f"(c.y), "+f"(c.z), "+f"(c.w)
        : "r"(a0), "r"(a1), "r"(a2), "r"(a3), "r"(b0), "r"(b1));
}

// split-pack two floats into (hi f16x2, lo-scaled f16x2)
static __device__ __forceinline__ void splitpack(float f0, float f1,
                                                 uint32_t& hi, uint32_t& lo) {
    __half h0 = __float2half_rn(f0);
    __half h1 = __float2half_rn(f1);
    float r0 = (f0 - __half2float(h0)) * 4096.f;
    float r1 = (f1 - __half2float(h1)) * 4096.f;
    __half2 hh = __halves2half2(h0, h1);                       // .x = f0 (low)
    __half2 ll = __halves2half2(__float2half_rn(r0), __float2half_rn(r1));
    hi = *(uint32_t*)&hh;
    lo = *(uint32_t*)&ll;
}

// ============ Kernel 1: 3-pass fp16 mma.sync distance GEMM + fused argmin ============
__global__ __launch_bounds__(NTH, 1)
void vq_argmin_mma(const float* __restrict__ x, const float* __restrict__ dict) {
    extern __shared__ char smem[];
    uint4* XF = (uint4*)(smem + SM_XF);
    uint4* BF = (uint4*)(smem + SM_BF);
    float* dsq = (float*)(smem + SM_DSQ);
    float* wmin = (float*)(smem + SM_WMIN);
    int*   widx = (int*)(smem + SM_WIDX);

    const int tid  = threadIdx.x;
    const int wid  = tid >> 5;
    const int lane = tid & 31;
    const int gid  = lane >> 2;        // 0..7
    const int tg   = lane & 3;         // 0..3
    const int m0   = (wid & 3) * 32;   // warp M origin
    const int wn   = wid >> 2;         // 0..1
    const int n0   = wn * 32;          // warp N origin

    const int c  = blockIdx.x;
    const int b0 = blockIdx.y * BM;

    // ---- XF fill: convert x tile once into fp16 hi/lo A-fragment layout ----
    {
        const int r = tid >> 1;        // 0..127
        const int half = tid & 1;      // which 64-col half
        const float* xr = x + (size_t)(b0 + r) * CW + (size_t)c * NE + half * 64;
        float4 xv[16];
        #pragma unroll
        for (int j = 0; j < 16; ++j) xv[j] = *(const float4*)(xr + j * 4);
        const float* pf = (const float*)xv;
        #pragma unroll
        for (int ksl = 0; ksl < 4; ++ksl) {
            const int ks = half * 4 + ksl;
            #pragma unroll
            for (int t = 0; t < 4; ++t) {
                const int l0 = ksl * 16 + 2 * t;
                uint32_t hA, lA, hB, lB;
                splitpack(pf[l0],     pf[l0 + 1], hA, lA);
                splitpack(pf[l0 + 8], pf[l0 + 9], hB, lB);
                XF[ks * 512 + r * 4 + t] = make_uint4(hA, hB, lA, lB);
            }
        }
    }

    // ---- per-thread state ----
    float4 ahh[2][4], amx[2][4];
    #pragma unroll
    for (int mt = 0; mt < 2; ++mt)
        #pragma unroll
        for (int nt = 0; nt < 4; ++nt) {
            ahh[mt][nt] = make_float4(0.f, 0.f, 0.f, 0.f);
            amx[mt][nt] = make_float4(0.f, 0.f, 0.f, 0.f);
        }

    float minv[4];
    int   mini[4];
    #pragma unroll
    for (int i = 0; i < 4; ++i) { minv[i] = 3.402823466e38f; mini[i] = 0; }

    // dict conversion role: 4 threads per dict row (32-col segment each)
    const int dn   = tid >> 2;     // 0..63
    const int tseg = tid & 3;      // 0..3
    const float* dbase = dict + (size_t)c * NS * NE + tseg * 32;

    float4 pre[8];
    {   // prefetch chunk 0
        const float* src = dbase + (size_t)dn * NE;
        #pragma unroll
        for (int j = 0; j < 8; ++j) pre[j] = *(const float4*)(src + j * 4);
    }

    // convert chunk 0 into buffer 0
    {
        const float* pf = (const float*)pre;
        float ss = 0.f;
        #pragma unroll
        for (int i = 0; i < 32; ++i) ss = fmaf(pf[i], pf[i], ss);
        #pragma unroll
        for (int j = 0; j < 2; ++j) {
            const int ks = tseg * 2 + j;
            #pragma unroll
            for (int t = 0; t < 4; ++t) {
                const int l0 = j * 16 + 2 * t;
                uint32_t hA, lA, hB, lB;
                splitpack(pf[l0],     pf[l0 + 1], hA, lA);
                splitpack(pf[l0 + 8], pf[l0 + 9], hB, lB);
                BF[ks * 256 + dn * 4 + t] = make_uint4(hA, hB, lA, lB);
            }
        }
        ss += __shfl_xor_sync(0xffffffffu, ss, 1);
        ss += __shfl_xor_sync(0xffffffffu, ss, 2);
        if (tseg == 0) dsq[dn] = ss;
    }
    __syncthreads();

    for (int s = 0; s < NCH; ++s) {
        const int p = s & 1;
        const uint4* BFp = BF + p * 2048;

        // ---- prefetch next chunk early (LDG latency hides under mma) ----
        if (s + 1 < NCH) {
            const float* src = dbase + (size_t)((s + 1) * BN + dn) * NE;
            #pragma unroll
            for (int j = 0; j < 8; ++j) pre[j] = *(const float4*)(src + j * 4);
        }

        // ---- mma phase: 8 k16-steps x (2m x 4n) x 3 passes ----
        #pragma unroll 4
        for (int ks = 0; ks < KS; ++ks) {
            uint4 A0[2], A1[2], Bv[4];
            #pragma unroll
            for (int mt = 0; mt < 2; ++mt) {
                A0[mt] = XF[ks * 512 + (m0 + mt * 16 + gid) * 4 + tg];
                A1[mt] = XF[ks * 512 + (m0 + mt * 16 + 8 + gid) * 4 + tg];
            }
            #pragma unroll
            for (int nt = 0; nt < 4; ++nt)
                Bv[nt] = BFp[ks * 256 + (n0 + nt * 8 + gid) * 4 + tg];

            // pass 1: hi*hi (8 independent accs)
            #pragma unroll
            for (int mt = 0; mt < 2; ++mt)
                #pragma unroll
                for (int nt = 0; nt < 4; ++nt)
                    mma_f16(ahh[mt][nt], A0[mt].x, A1[mt].x, A0[mt].y, A1[mt].y,
                            Bv[nt].x, Bv[nt].y);
            // pass 2: hi_x * lo_d  (8 independent accs)
            #pragma unroll
            for (int mt = 0; mt < 2; ++mt)
                #pragma unroll
                for (int nt = 0; nt < 4; ++nt)
                    mma_f16(amx[mt][nt], A0[mt].x, A1[mt].x, A0[mt].y, A1[mt].y,
                            Bv[nt].z, Bv[nt].w);
            // pass 3: lo_x * hi_d  (dependent on pass 2, 8 apart)
            #pragma unroll
            for (int mt = 0; mt < 2; ++mt)
                #pragma unroll
                for (int nt = 0; nt < 4; ++nt)
                    mma_f16(amx[mt][nt], A0[mt].z, A1[mt].z, A0[mt].w, A1[mt].w,
                            Bv[nt].x, Bv[nt].y);
        }

        // ---- convert chunk s+1 into other buffer ----
        if (s + 1 < NCH) {
            const int q = (s + 1) & 1;
            uint4* BFq = BF + q * 2048;
            const float* pf = (const float*)pre;
            float ss = 0.f;
            #pragma unroll
            for (int i = 0; i < 32; ++i) ss = fmaf(pf[i], pf[i], ss);
            #pragma unroll
            for (int j = 0; j < 2; ++j) {
                const int ks = tseg * 2 + j;
                #pragma unroll
                for (int t = 0; t < 4; ++t) {
                    const int l0 = j * 16 + 2 * t;
                    uint32_t hA, lA, hB, lB;
                    splitpack(pf[l0],     pf[l0 + 1], hA, lA);
                    splitpack(pf[l0 + 8], pf[l0 + 9], hB, lB);
                    BFq[ks * 256 + dn * 4 + t] = make_uint4(hA, hB, lA, lB);
                }
            }
            ss += __shfl_xor_sync(0xffffffffu, ss, 1);
            ss += __shfl_xor_sync(0xffffffffu, ss, 2);
            if (tseg == 0) dsq[q * 64 + dn] = ss;
        }

        // ---- epilogue: score + running argmin, reset accs ----
        const int sbase = s * BN;
        #pragma unroll
        for (int mt = 0; mt < 2; ++mt) {
            #pragma unroll
            for (int nt = 0; nt < 4; ++nt) {
                const int colb = n0 + nt * 8 + 2 * tg;
                const float d0 = dsq[p * 64 + colb];
                const float d1 = dsq[p * 64 + colb + 1];
                float4 hh = ahh[mt][nt];
                float4 mx = amx[mt][nt];
                const float cx0 = fmaf(mx.x, INV4096, hh.x);
                const float cx1 = fmaf(mx.y, INV4096, hh.y);
                const float cx2 = fmaf(mx.z, INV4096, hh.z);
                const float cx3 = fmaf(mx.w, INV4096, hh.w);
                const int i0 = sbase + colb;
                // row gid (slot mt*2)
                {
                    float s0 = fmaf(-2.f, cx0, d0);
                    float s1 = fmaf(-2.f, cx1, d1);
                    if (s0 < minv[mt * 2]) { minv[mt * 2] = s0; mini[mt * 2] = i0; }
                    if (s1 < minv[mt * 2]) { minv[mt * 2] = s1; mini[mt * 2] = i0 + 1; }
                }
                // row gid+8 (slot mt*2+1)
                {
                    float s0 = fmaf(-2.f, cx2, d0);
                    float s1 = fmaf(-2.f, cx3, d1);
                    if (s0 < minv[mt * 2 + 1]) { minv[mt * 2 + 1] = s0; mini[mt * 2 + 1] = i0; }
                    if (s1 < minv[mt * 2 + 1]) { minv[mt * 2 + 1] = s1; mini[mt * 2 + 1] = i0 + 1; }
                }
                ahh[mt][nt] = make_float4(0.f, 0.f, 0.f, 0.f);
                amx[mt][nt] = make_float4(0.f, 0.f, 0.f, 0.f);
            }
        }
        __syncthreads();   // BF buffer handoff
    }

    // ---- reduce across tg lanes (same row), then across the 2 n-warps ----
    #pragma unroll
    for (int slot = 0; slot < 4; ++slot) {
        float v  = minv[slot];
        int   ix = mini[slot];
        #pragma unroll
        for (int off = 1; off <= 2; off <<= 1) {
            float ov = __shfl_xor_sync(0xffffffffu, v, off);
            int   oi = __shfl_xor_sync(0xffffffffu, ix, off);
            if (ov < v || (ov == v && oi < ix)) { v = ov; ix = oi; }
        }
        if (tg == 0) {
            const int r = m0 + (slot >> 1) * 16 + (slot & 1) * 8 + gid;
            wmin[wn * 128 + r] = v;
            widx[wn * 128 + r] = ix;
        }
    }
    __syncthreads();
    if (tid < 128) {
        const float v0 = wmin[tid], v1 = wmin[128 + tid];
        const int   i0 = widx[tid], i1 = widx[128 + tid];
        int best = (v1 < v0 || (v1 == v0 && i1 < i0)) ? i1 : i0;
        g_argmin[(size_t)(b0 + tid) * NC + c] = best;
    }
}

// ============ Kernel 2: gather codewords + stream one-hot ============
__global__ __launch_bounds__(256)
void vq_output_kernel(const float* __restrict__ dict, float* __restrict__ out) {
    const int bc = blockIdx.x;        // b*NC + c
    const int b  = bc >> 6;
    const int c  = bc & 63;
    const int idx = g_argmin[bc];
    const int t  = threadIdx.x;

    if (t < 32) {
        const float4* src = (const float4*)(dict + ((size_t)c * NS + idx) * NE);
        float4* dst = (float4*)(out + (size_t)b * CW + c * NE);
        dst[t] = src[t];
    }

    float4* oh = (float4*)(out + (size_t)EMBED_ELEMS + (size_t)bc * NS);
    const int qi = idx >> 2;
    const int ri = idx & 3;
    #pragma unroll
    for (int it = 0; it < 4; ++it) {
        const int pidx = t + it * 256;
        float4 v = make_float4(0.f, 0.f, 0.f, 0.f);
        if (pidx == qi) {
            v.x = (ri == 0) ? 1.f : 0.f;
            v.y = (ri == 1) ? 1.f : 0.f;
            v.z = (ri == 2) ? 1.f : 0.f;
            v.w = (ri == 3) ? 1.f : 0.f;
        }
        __stwt(&oh[pidx], v);   // streaming store: one-hot is never re-read
    }
}

extern "C" void kernel_launch(void* const* d_in, const int* in_sizes, int n_in,
                              void* d_out, int out_size) {
    const float* x    = (const float*)d_in[0];   // [256, 8192]
    const float* dict = (const float*)d_in[1];   // [64, 4096, 128]
    float* out = (float*)d_out;

    cudaFuncSetAttribute(vq_argmin_mma,
                         cudaFuncAttributeMaxDynamicSharedMemorySize, SM_TOTAL);

    vq_argmin_mma<<<dim3(NC, BATCH / BM), NTH, SM_TOTAL>>>(x, dict);
    vq_output_kernel<<<BATCH * NC, 256>>>(dict, out);
}

// round 6
// speedup vs baseline: 2.7432x; 1.0066x over previous
#include <cuda_runtime.h>
#include <cuda_fp16.h>
#include <cstdint>

// Problem constants
#define BATCH 256
#define CW    8192
#define NC    64
#define NS    4096
#define NE    128
#define BM    128            // batch rows per CTA
#define BN    64             // dict entries per chunk
#define NCH   (NS / BN)      // 64 chunks
#define KS    8              // k-steps of 16
#define NTH   256

#define EMBED_ELEMS (BATCH * CW)
#define INV4096 2.44140625e-4f

__device__ int g_argmin[BATCH * NC];

// ---- smem layout (bytes) ----
#define SM_XF   0            // [8 ks][128 r][4 tg] uint4 = 65536
#define SM_BF   65536        // 2 x [8 ks][64 n][4 tg] uint4 = 65536
#define SM_DSQ  131072       // [2][64] float
#define SM_WMIN 131584       // [2][128] float
#define SM_WIDX 132608       // [2][128] int
#define SM_TOTAL 133632

static __device__ __forceinline__ void mma_f16_f32(float4& c, uint32_t a0, uint32_t a1,
                                                   uint32_t a2, uint32_t a3,
                                                   uint32_t b0, uint32_t b1) {
    asm("mma.sync.aligned.m16n8k16.row.col.f32.f16.f16.f32 "
        "{%0,%1,%2,%3}, {%4,%5,%6,%7}, {%8,%9}, {%0,%1,%2,%3};"
        : "+f"(c.x), "+f"(c.y), "+f"(c.z), "+f"(c.w)
        : "r"(a0), "r"(a1), "r"(a2), "r"(a3), "r"(b0), "r"(b1));
}

// f16-accumulator variant: c0 = rows gid (cols 2tg,2tg+1 as half2), c1 = rows gid+8
static __device__ __forceinline__ void mma_f16_f16(uint32_t& c0, uint32_t& c1,
                                                   uint32_t a0, uint32_t a1,
                                                   uint32_t a2, uint32_t a3,
                                                   uint32_t b0, uint32_t b1) {
    asm("mma.sync.aligned.m16n8k16.row.col.f16.f16.f16.f16 "
        "{%0,%1}, {%2,%3,%4,%5}, {%6,%7}, {%0,%1};"
        : "+r"(c0), "+r"(c1)
        : "r"(a0), "r"(a1), "r"(a2), "r"(a3), "r"(b0), "r"(b1));
}

// split-pack two floats into (hi f16x2, lo-scaled f16x2)
static __device__ __forceinline__ void splitpack(float f0, float f1,
                                                 uint32_t& hi, uint32_t& lo) {
    __half h0 = __float2half_rn(f0);
    __half h1 = __float2half_rn(f1);
    float r0 = (f0 - __half2float(h0)) * 4096.f;
    float r1 = (f1 - __half2float(h1)) * 4096.f;
    __half2 hh = __halves2half2(h0, h1);
    __half2 ll = __halves2half2(__float2half_rn(r0), __float2half_rn(r1));
    hi = *(uint32_t*)&hh;
    lo = *(uint32_t*)&ll;
}

// ============ Kernel 1: 3-pass fp16 mma distance GEMM + argmin + one-hot zeros + embed ============
__global__ __launch_bounds__(NTH, 1)
void vq_argmin_mma(const float* __restrict__ x, const float* __restrict__ dict,
                   float* __restrict__ out) {
    extern __shared__ char smem[];
    uint4* XF = (uint4*)(smem + SM_XF);
    uint4* BF = (uint4*)(smem + SM_BF);
    float* dsq = (float*)(smem + SM_DSQ);
    float* wmin = (float*)(smem + SM_WMIN);
    int*   widx = (int*)(smem + SM_WIDX);

    const int tid  = threadIdx.x;
    const int wid  = tid >> 5;
    const int lane = tid & 31;
    const int gid  = lane >> 2;        // 0..7
    const int tg   = lane & 3;         // 0..3
    const int m0   = (wid & 3) * 32;   // warp M origin
    const int wn   = wid >> 2;         // 0..1
    const int n0   = wn * 32;          // warp N origin

    const int c  = blockIdx.x;
    const int b0 = blockIdx.y * BM;

    // ---- XF fill: convert x tile once into fp16 hi/lo A-fragment layout ----
    {
        const int r = tid >> 1;
        const int half = tid & 1;
        const float* xr = x + (size_t)(b0 + r) * CW + (size_t)c * NE + half * 64;
        float4 xv[16];
        #pragma unroll
        for (int j = 0; j < 16; ++j) xv[j] = *(const float4*)(xr + j * 4);
        const float* pf = (const float*)xv;
        #pragma unroll
        for (int ksl = 0; ksl < 4; ++ksl) {
            const int ks = half * 4 + ksl;
            #pragma unroll
            for (int t = 0; t < 4; ++t) {
                const int l0 = ksl * 16 + 2 * t;
                uint32_t hA, lA, hB, lB;
                splitpack(pf[l0],     pf[l0 + 1], hA, lA);
                splitpack(pf[l0 + 8], pf[l0 + 9], hB, lB);
                XF[ks * 512 + r * 4 + t] = make_uint4(hA, hB, lA, lB);
            }
        }
    }

    // ---- per-thread state ----
    float4 ahh[2][4];
    uint2  amx[2][4];                  // f16x2 accumulators (correction)
    #pragma unroll
    for (int mt = 0; mt < 2; ++mt)
        #pragma unroll
        for (int nt = 0; nt < 4; ++nt) {
            ahh[mt][nt] = make_float4(0.f, 0.f, 0.f, 0.f);
            amx[mt][nt] = make_uint2(0u, 0u);
        }

    float minv[4];
    int   mini[4];
    #pragma unroll
    for (int i = 0; i < 4; ++i) { minv[i] = 3.402823466e38f; mini[i] = 0; }

    // dict conversion role: 4 threads per dict row
    const int dn   = tid >> 2;
    const int tseg = tid & 3;
    const float* dbase = dict + (size_t)c * NS * NE + tseg * 32;

    // one-hot zero-fill role: 16 threads per row, 8 row-passes
    const int zr = tid >> 4;           // 0..15
    const int zc = (tid & 15) * 4;     // 0..60

    float4 pre[8];
    {   // prefetch chunk 0
        const float* src = dbase + (size_t)dn * NE;
        #pragma unroll
        for (int j = 0; j < 8; ++j) pre[j] = *(const float4*)(src + j * 4);
    }

    // convert chunk 0 into buffer 0
    {
        const float* pf = (const float*)pre;
        float ss = 0.f;
        #pragma unroll
        for (int i = 0; i < 32; ++i) ss = fmaf(pf[i], pf[i], ss);
        #pragma unroll
        for (int j = 0; j < 2; ++j) {
            const int ks = tseg * 2 + j;
            #pragma unroll
            for (int t = 0; t < 4; ++t) {
                const int l0 = j * 16 + 2 * t;
                uint32_t hA, lA, hB, lB;
                splitpack(pf[l0],     pf[l0 + 1], hA, lA);
                splitpack(pf[l0 + 8], pf[l0 + 9], hB, lB);
                BF[ks * 256 + dn * 4 + t] = make_uint4(hA, hB, lA, lB);
            }
        }
        ss += __shfl_xor_sync(0xffffffffu, ss, 1);
        ss += __shfl_xor_sync(0xffffffffu, ss, 2);
        if (tseg == 0) dsq[dn] = ss;
    }
    __syncthreads();

    for (int s = 0; s < NCH; ++s) {
        const int p = s & 1;
        const uint4* BFp = BF + p * 2048;

        // ---- prefetch next chunk ----
        if (s + 1 < NCH) {
            const float* src = dbase + (size_t)((s + 1) * BN + dn) * NE;
            #pragma unroll
            for (int j = 0; j < 8; ++j) pre[j] = *(const float4*)(src + j * 4);
        }

        // ---- one-hot zero-fill: segment s of all 128 owned rows (idle DRAM BW) ----
        {
            const size_t seg = (size_t)EMBED_ELEMS + (size_t)s * BN + zc;
            #pragma unroll
            for (int pz = 0; pz < 8; ++pz) {
                const int r = pz * 16 + zr;
                float4* dst = (float4*)(out + seg + ((size_t)(b0 + r) * NC + c) * NS);
                __stwt(dst, make_float4(0.f, 0.f, 0.f, 0.f));
            }
        }

        // ---- mma phase ----
        #pragma unroll 4
        for (int ks = 0; ks < KS; ++ks) {
            uint4 A0[2], A1[2], Bv[4];
            #pragma unroll
            for (int mt = 0; mt < 2; ++mt) {
                A0[mt] = XF[ks * 512 + (m0 + mt * 16 + gid) * 4 + tg];
                A1[mt] = XF[ks * 512 + (m0 + mt * 16 + 8 + gid) * 4 + tg];
            }
            #pragma unroll
            for (int nt = 0; nt < 4; ++nt)
                Bv[nt] = BFp[ks * 256 + (n0 + nt * 8 + gid) * 4 + tg];

            // pass 1: hi*hi, f32 acc
            #pragma unroll
            for (int mt = 0; mt < 2; ++mt)
                #pragma unroll
                for (int nt = 0; nt < 4; ++nt)
                    mma_f16_f32(ahh[mt][nt], A0[mt].x, A1[mt].x, A0[mt].y, A1[mt].y,
                                Bv[nt].x, Bv[nt].y);
            // pass 2: hi_x * lo_d, f16 acc
            #pragma unroll
            for (int mt = 0; mt < 2; ++mt)
                #pragma unroll
                for (int nt = 0; nt < 4; ++nt)
                    mma_f16_f16(amx[mt][nt].x, amx[mt][nt].y,
                                A0[mt].x, A1[mt].x, A0[mt].y, A1[mt].y,
                                Bv[nt].z, Bv[nt].w);
            // pass 3: lo_x * hi_d, f16 acc
            #pragma unroll
            for (int mt = 0; mt < 2; ++mt)
                #pragma unroll
                for (int nt = 0; nt < 4; ++nt)
                    mma_f16_f16(amx[mt][nt].x, amx[mt][nt].y,
                                A0[mt].z, A1[mt].z, A0[mt].w, A1[mt].w,
                                Bv[nt].x, Bv[nt].y);
        }

        // ---- convert chunk s+1 into other buffer ----
        if (s + 1 < NCH) {
            const int q = (s + 1) & 1;
            uint4* BFq = BF + q * 2048;
            const float* pf = (const float*)pre;
            float ss = 0.f;
            #pragma unroll
            for (int i = 0; i < 32; ++i) ss = fmaf(pf[i], pf[i], ss);
            #pragma unroll
            for (int j = 0; j < 2; ++j) {
                const int ks = tseg * 2 + j;
                #pragma unroll
                for (int t = 0; t < 4; ++t) {
                    const int l0 = j * 16 + 2 * t;
                    uint32_t hA, lA, hB, lB;
                    splitpack(pf[l0],     pf[l0 + 1], hA, lA);
                    splitpack(pf[l0 + 8], pf[l0 + 9], hB, lB);
                    BFq[ks * 256 + dn * 4 + t] = make_uint4(hA, hB, lA, lB);
                }
            }
            ss += __shfl_xor_sync(0xffffffffu, ss, 1);
            ss += __shfl_xor_sync(0xffffffffu, ss, 2);
            if (tseg == 0) dsq[q * 64 + dn] = ss;
        }

        // ---- epilogue: score + running argmin, reset accs ----
        const int sbase = s * BN;
        #pragma unroll
        for (int mt = 0; mt < 2; ++mt) {
            #pragma unroll
            for (int nt = 0; nt < 4; ++nt) {
                const int colb = n0 + nt * 8 + 2 * tg;
                const float d0 = dsq[p * 64 + colb];
                const float d1 = dsq[p * 64 + colb + 1];
                float4 hh = ahh[mt][nt];
                float2 mlo = __half22float2(*(__half2*)&amx[mt][nt].x);  // rows gid
                float2 mhi = __half22float2(*(__half2*)&amx[mt][nt].y);  // rows gid+8
                const float cx0 = fmaf(mlo.x, INV4096, hh.x);
                const float cx1 = fmaf(mlo.y, INV4096, hh.y);
                const float cx2 = fmaf(mhi.x, INV4096, hh.z);
                const float cx3 = fmaf(mhi.y, INV4096, hh.w);
                const int i0 = sbase + colb;
                {
                    float s0 = fmaf(-2.f, cx0, d0);
                    float s1 = fmaf(-2.f, cx1, d1);
                    if (s0 < minv[mt * 2]) { minv[mt * 2] = s0; mini[mt * 2] = i0; }
                    if (s1 < minv[mt * 2]) { minv[mt * 2] = s1; mini[mt * 2] = i0 + 1; }
                }
                {
                    float s0 = fmaf(-2.f, cx2, d0);
                    float s1 = fmaf(-2.f, cx3, d1);
                    if (s0 < minv[mt * 2 + 1]) { minv[mt * 2 + 1] = s0; mini[mt * 2 + 1] = i0; }
                    if (s1 < minv[mt * 2 + 1]) { minv[mt * 2 + 1] = s1; mini[mt * 2 + 1] = i0 + 1; }
                }
                ahh[mt][nt] = make_float4(0.f, 0.f, 0.f, 0.f);
                amx[mt][nt] = make_uint2(0u, 0u);
            }
        }
        __syncthreads();
    }

    // ---- reduce across tg lanes, then across the 2 n-warps ----
    #pragma unroll
    for (int slot = 0; slot < 4; ++slot) {
        float v  = minv[slot];
        int   ix = mini[slot];
        #pragma unroll
        for (int off = 1; off <= 2; off <<= 1) {
            float ov = __shfl_xor_sync(0xffffffffu, v, off);
            int   oi = __shfl_xor_sync(0xffffffffu, ix, off);
            if (ov < v || (ov == v && oi < ix)) { v = ov; ix = oi; }
        }
        if (tg == 0) {
            const int r = m0 + (slot >> 1) * 16 + (slot & 1) * 8 + gid;
            wmin[wn * 128 + r] = v;
            widx[wn * 128 + r] = ix;
        }
    }
    __syncthreads();
    if (tid < 128) {
        const float v0 = wmin[tid], v1 = wmin[128 + tid];
        const int   i0 = widx[tid], i1 = widx[128 + tid];
        int best = (v1 < v0 || (v1 == v0 && i1 < i0)) ? i1 : i0;
        g_argmin[(size_t)(b0 + tid) * NC + c] = best;
        widx[tid] = best;               // stash for the gather below
    }
    __syncthreads();

    // ---- gather nearest codewords into the embed region (2 threads / row) ----
    {
        const int r = tid >> 1;
        const int half = tid & 1;
        const int ix = widx[r];
        const float4* src = (const float4*)(dict + ((size_t)c * NS + ix) * NE) + half * 16;
        float4* dst = (float4*)(out + (size_t)(b0 + r) * CW + c * NE) + half * 16;
        #pragma unroll
        for (int j = 0; j < 16; ++j) __stwt(&dst[j], src[j]);
    }
}

// ============ Kernel 2: scatter the 16384 ones ============
__global__ __launch_bounds__(256)
void vq_ones_kernel(float* __restrict__ out) {
    const int bc = blockIdx.x * 256 + threadIdx.x;   // b*NC + c
    const int idx = g_argmin[bc];
    out[(size_t)EMBED_ELEMS + (size_t)bc * NS + idx] = 1.0f;
}

extern "C" void kernel_launch(void* const* d_in, const int* in_sizes, int n_in,
                              void* d_out, int out_size) {
    const float* x    = (const float*)d_in[0];   // [256, 8192]
    const float* dict = (const float*)d_in[1];   // [64, 4096, 128]
    float* out = (float*)d_out;

    cudaFuncSetAttribute(vq_argmin_mma,
                         cudaFuncAttributeMaxDynamicSharedMemorySize, SM_TOTAL);

    vq_argmin_mma<<<dim3(NC, BATCH / BM), NTH, SM_TOTAL>>>(x, dict, out);
    vq_ones_kernel<<<BATCH * NC / 256, 256>>>(out);
}